// round 16
// baseline (speedup 1.0000x reference)
#include <cuda_runtime.h>
#include <cuda_bf16.h>
#include <cstdint>
#include <math.h>

#define B_ 4
#define N_ 4096
#define D_ 1024
#define G_ 4
#define H_ 8
#define DH_ 64
#define DI_ 512
#define NQ_ 1024
#define NK_ 512
#define NKV_ 513
#define NKVP_ 576

// ---------------- scratch ---------------------------------------------------
__device__ float         g_qlog [B_*G_*N_];
__device__ float         g_kvlog[B_*G_*N_];
__device__ int           g_qidx [B_*G_*NQ_];
__device__ float         g_qscore[B_*G_*NQ_];
__device__ int           g_kvidx [B_*G_*NK_];
__device__ float         g_sscale[B_*G_*NKVP_];
__device__ int           g_slot [B_*G_*N_];
__device__ __nv_bfloat16 g_xbf  [B_*N_*D_];
__device__ __nv_bfloat16 g_wqbf [G_*DI_*D_];
__device__ __nv_bfloat16 g_wkvbf[G_*2*DI_*D_];
__device__ __nv_bfloat16 g_woutbf[G_*D_*DI_];
__device__ __nv_bfloat16 g_nullbf[2*G_*H_*DH_];
__device__ __nv_bfloat16 g_q    [B_*G_*NQ_*DI_];
__device__ __nv_bfloat16 g_kv   [B_*G_*NK_*2*DI_];
__device__ __nv_bfloat16 g_attno[B_*G_*NQ_*DI_];
__device__ float         g_of   [(size_t)B_*G_*NQ_*D_];

#define QSCALE 0.18033688f   // DH^-0.5 * log2(e)

// ---------------- helpers ---------------------------------------------------
__device__ __forceinline__ uint32_t f2bf2(float lo, float hi) {
    uint32_t r;
    asm("cvt.rn.bf16x2.f32 %0, %1, %2;" : "=r"(r) : "f"(hi), "f"(lo));
    return r;
}
__device__ __forceinline__ float2 bf2f2(uint32_t v) {
    __nv_bfloat162 b = *(__nv_bfloat162*)&v;
    return __bfloat1622float2(b);
}
__device__ __forceinline__ float ex2f(float x) {
    float y;
    asm("ex2.approx.f32 %0, %1;" : "=f"(y) : "f"(x));
    return y;
}
__device__ __forceinline__ void mma_bf16(float c[4],
                                         uint32_t a0, uint32_t a1, uint32_t a2, uint32_t a3,
                                         uint32_t b0, uint32_t b1) {
    asm volatile(
        "mma.sync.aligned.m16n8k16.row.col.f32.bf16.bf16.f32 "
        "{%0,%1,%2,%3}, {%4,%5,%6,%7}, {%8,%9}, {%0,%1,%2,%3};\n"
        : "+f"(c[0]), "+f"(c[1]), "+f"(c[2]), "+f"(c[3])
        : "r"(a0), "r"(a1), "r"(a2), "r"(a3), "r"(b0), "r"(b1));
}
__device__ __forceinline__ void ldsm_x4(uint32_t& r0, uint32_t& r1, uint32_t& r2, uint32_t& r3,
                                        uint32_t addr) {
    asm volatile("ldmatrix.sync.aligned.m8n8.x4.shared.b16 {%0,%1,%2,%3}, [%4];"
                 : "=r"(r0), "=r"(r1), "=r"(r2), "=r"(r3) : "r"(addr));
}
__device__ __forceinline__ void ldsm_x4_t(uint32_t& r0, uint32_t& r1, uint32_t& r2, uint32_t& r3,
                                          uint32_t addr) {
    asm volatile("ldmatrix.sync.aligned.m8n8.x4.trans.shared.b16 {%0,%1,%2,%3}, [%4];"
                 : "=r"(r0), "=r"(r1), "=r"(r2), "=r"(r3) : "r"(addr));
}
__device__ __forceinline__ void cp_async16(void* smem_dst, const void* gmem_src) {
    uint32_t s = (uint32_t)__cvta_generic_to_shared(smem_dst);
    asm volatile("cp.async.cg.shared.global [%0], [%1], 16;\n" :: "r"(s), "l"(gmem_src));
}
__device__ __forceinline__ void cp_commit() { asm volatile("cp.async.commit_group;\n"); }
__device__ __forceinline__ void cp_wait0() { asm volatile("cp.async.wait_group 0;\n"); }
__device__ __forceinline__ void cp_wait1() { asm volatile("cp.async.wait_group 1;\n"); }

// ---------------- 0) fp32 -> bf16 convert (weights + null_kv) ---------------
#define WQ4   (G_*DI_*D_/4)
#define WKV4  (G_*2*DI_*D_/4)
#define WOUT4 (G_*D_*DI_/4)
#define NUL4  (2*G_*H_*DH_/4)
__device__ __forceinline__ void cvt4(const float* s, __nv_bfloat16* d, int i) {
    float4 v = ((const float4*)s)[i];
    ((uint2*)d)[i] = make_uint2(f2bf2(v.x, v.y), f2bf2(v.z, v.w));
}
__global__ void cvt_all(const float* __restrict__ wq, const float* __restrict__ wkv,
                        const float* __restrict__ wout, const float* __restrict__ nul)
{
    int i = blockIdx.x*256 + threadIdx.x;
    if (i < WQ4) { cvt4(wq, g_wqbf, i); return; }
    i -= WQ4;
    if (i < WKV4) { cvt4(wkv, g_wkvbf, i); return; }
    i -= WKV4;
    if (i < WOUT4) { cvt4(wout, g_woutbf, i); return; }
    i -= WOUT4;
    if (i < NUL4) cvt4(nul, g_nullbf, i);
}

// ---------------- 1) router logits (fp32) + x -> bf16 -----------------------
__global__ void __launch_bounds__(512) logits_kernel(const float* __restrict__ x,
                                                     const float* __restrict__ w_qr,
                                                     const float* __restrict__ w_kvr)
{
    __shared__ float ws[8*D_];
    int tid = threadIdx.x;
    for (int i = tid; i < 4*D_; i += 512) { ws[i] = w_qr[i]; ws[4*D_+i] = w_kvr[i]; }
    __syncthreads();
    int warp = tid >> 5, lane = tid & 31;
    int tok = blockIdx.x*16 + warp;
    int b = tok / N_, n = tok % N_;
    const float4* xr = (const float4*)(x + (size_t)tok*D_);
    uint2* xt = (uint2*)(g_xbf + (size_t)tok*D_);
    float acc[8] = {0,0,0,0,0,0,0,0};
    #pragma unroll
    for (int it = 0; it < 8; it++) {
        int k4 = lane + it*32;
        float4 xv = xr[k4];
        xt[k4] = make_uint2(f2bf2(xv.x, xv.y), f2bf2(xv.z, xv.w));
        #pragma unroll
        for (int g = 0; g < 8; g++) {
            float4 w4 = *(const float4*)(ws + g*D_ + k4*4);
            acc[g] += xv.x*w4.x + xv.y*w4.y + xv.z*w4.z + xv.w*w4.w;
        }
    }
    #pragma unroll
    for (int g = 0; g < 8; g++) {
        #pragma unroll
        for (int o = 16; o > 0; o >>= 1) acc[g] += __shfl_xor_sync(0xffffffffu, acc[g], o);
    }
    if (lane < 4) {
        g_qlog[(b*G_+lane)*N_ + n] = acc[lane];
        g_slot[(b*G_+lane)*N_ + n] = -1;
    } else if (lane < 8) {
        g_kvlog[(b*G_+(lane-4))*N_ + n] = acc[lane];
    }
}

// ---------------- 2) exact top-k via deterministic radix select -------------
__global__ void __launch_bounds__(1024) topk_kernel()
{
    __shared__ uint32_t su[N_];
    __shared__ int hist[256];
    __shared__ int wsum[32];
    __shared__ int sBase;
    __shared__ uint32_t sPref;
    __shared__ int sK;

    const bool isq = blockIdx.x < (B_*G_);
    const int bg = isq ? blockIdx.x : blockIdx.x - B_*G_;
    const int ksel = isq ? NQ_ : NK_;
    const float* L = (isq ? g_qlog : g_kvlog) + (size_t)bg*N_;
    const int tid = threadIdx.x, warp = tid >> 5, lane = tid & 31;

    for (int i = tid; i < N_; i += 1024) {
        uint32_t u = __float_as_uint(L[i]);
        su[i] = (u & 0x80000000u) ? ~u : (u | 0x80000000u);
    }
    if (tid == 0) { sK = ksel; sPref = 0; sBase = 0; }
    __syncthreads();

    for (int p = 0; p < 4; p++) {
        const int shift = 24 - 8*p;
        for (int i = tid; i < 256; i += 1024) hist[i] = 0;
        __syncthreads();
        const uint32_t pref = sPref;
        const int kk = sK;
        for (int i = tid; i < N_; i += 1024) {
            uint32_t u = su[i];
            bool act = (p == 0) ? true : ((u >> (shift + 8)) == pref);
            if (act) atomicAdd(&hist[(u >> shift) & 0xFF], 1);
        }
        __syncthreads();
        if (tid == 0) {
            int acc = 0, b = 255;
            for (; b > 0; b--) {
                if (acc + hist[b] >= kk) break;
                acc += hist[b];
            }
            sPref = (p == 0) ? (uint32_t)b : ((pref << 8) | (uint32_t)b);
            sK = kk - acc;
        }
        __syncthreads();
    }
    const uint32_t T = sPref;
    for (int pass = 0; pass < 2; pass++) {
        for (int r = 0; r < 4; r++) {
            const int i = r*1024 + tid;
            const uint32_t u = su[i];
            const bool sel = pass == 0 ? (u > T) : (u == T);
            const uint32_t bal = __ballot_sync(0xffffffffu, sel);
            const int wpre = __popc(bal & ((1u << lane) - 1u));
            if (lane == 0) wsum[warp] = __popc(bal);
            __syncthreads();
            if (tid == 0) {
                int run = sBase;
                #pragma unroll
                for (int w = 0; w < 32; w++) { int c = wsum[w]; wsum[w] = run; run += c; }
                sBase = run;
            }
            __syncthreads();
            if (sel) {
                int pos = wsum[warp] + wpre;
                if (pos < ksel) {
                    uint32_t ob = (u & 0x80000000u) ? (u ^ 0x80000000u) : ~u;
                    float f = __uint_as_float(ob);
                    float score = 1.0f/(1.0f + expf(-f));
                    if (isq) {
                        g_qidx[bg*NQ_ + pos]   = i;
                        g_qscore[bg*NQ_ + pos] = score;
                        g_slot[(size_t)bg*N_ + i] = pos;
                    } else {
                        g_kvidx[bg*NK_ + pos] = i;
                        g_sscale[bg*NKVP_ + pos] = score;
                    }
                }
            }
            __syncthreads();
        }
    }
}

// ---------------- 3) 3-stage bf16 GEMM, one sync per chunk ------------------
template<int BM,int BN,int BK,bool GATHER,bool OUT_BF16>
__global__ void __launch_bounds__(256, 2)
mma_gemm(const __nv_bfloat16* __restrict__ A, int lda, int zdivA, long sA1, long sA2,
         const __nv_bfloat16* __restrict__ Bp, int ldb, int zdivB, long sB1, long sB2,
         void* __restrict__ Cv, int ldc, int zdivC, long sC1, long sC2,
         int K,
         const int* __restrict__ gidx, int gstride,
         const float* __restrict__ rowScale, int rsStride,
         float cscale)
{
    constexpr int WM = BM/2, WN = BN/4;
    constexpr int MI = WM/16, NI = WN/8;
    constexpr int BKP2 = BK/2 + 4;
    constexpr int ASTG = BM*BKP2, BSTG = BN*BKP2;

    extern __shared__ uint32_t dsm[];
    uint32_t* Asf = dsm;
    uint32_t* Bsf = dsm + 3*ASTG;
    int*      ridx = (int*)(dsm + 3*ASTG + 3*BSTG);

    const int z = blockIdx.z;
    A  += (long)(z/zdivA)*sA1 + (long)(z%zdivA)*sA2;
    Bp += (long)(z/zdivB)*sB1 + (long)(z%zdivB)*sB2;
    const int m0 = blockIdx.y*BM, n0 = blockIdx.x*BN;
    const int tid  = threadIdx.x;
    const int warp = tid >> 5, lane = tid & 31;
    const int gid  = lane >> 2, tig = lane & 3;
    const int wm0  = (warp >> 2) * WM;
    const int wn0  = (warp & 3) * WN;

    if (GATHER) {
        for (int i = tid; i < BM; i += 256) ridx[i] = gidx[z*gstride + m0 + i];
        __syncthreads();
    }

    auto prefetch = [&](int k0, int s) {
        uint32_t* As_ = Asf + s*ASTG;
        #pragma unroll
        for (int f = tid; f < BM*(BK/8); f += 256) {
            int m = f / (BK/8), c = f % (BK/8);
            long row = GATHER ? (long)ridx[m] : (long)(m0+m);
            cp_async16(&As_[m*BKP2 + c*4], A + row*(long)lda + k0 + c*8);
        }
        uint32_t* Bs_ = Bsf + s*BSTG;
        #pragma unroll
        for (int f = tid; f < BN*(BK/8); f += 256) {
            int nn = f / (BK/8), c = f % (BK/8);
            cp_async16(&Bs_[nn*BKP2 + c*4], Bp + (long)(n0+nn)*ldb + k0 + c*8);
        }
        cp_commit();
    };

    float acc[MI][NI][4];
    #pragma unroll
    for (int mi=0;mi<MI;mi++)
        #pragma unroll
        for (int ni=0;ni<NI;ni++)
            #pragma unroll
            for (int r=0;r<4;r++) acc[mi][ni][r] = 0.f;

    const uint32_t AsA = (uint32_t)__cvta_generic_to_shared(Asf);
    const uint32_t BsA = (uint32_t)__cvta_generic_to_shared(Bsf);
    const int lm = lane >> 3, lr = lane & 7;
    const uint32_t aLane = (uint32_t)(((wm0 + (lm&1)*8 + lr)*BKP2 + (lm>>1)*4) * 4);
    const uint32_t bLane = (uint32_t)(((wn0 + (lm>>1)*8 + lr)*BKP2 + (lm&1)*4) * 4);

    const int NKIT = K / BK;
    prefetch(0, 0);
    if (NKIT > 1) prefetch(BK, 1);
    for (int j = 0; j < NKIT; j++) {
        if (j + 1 < NKIT) cp_wait1(); else cp_wait0();
        __syncthreads();
        if (j + 2 < NKIT) prefetch((j+2)*BK, (j+2)%3);

        const uint32_t AsJ = AsA + (uint32_t)((j%3)*ASTG*4) + aLane;
        const uint32_t BsJ = BsA + (uint32_t)((j%3)*BSTG*4) + bLane;
        #pragma unroll
        for (int kk = 0; kk < BK/16; kk++) {
            uint32_t a[MI][4];
            uint32_t b[NI][2];
            #pragma unroll
            for (int mi=0;mi<MI;mi++)
                ldsm_x4(a[mi][0], a[mi][1], a[mi][2], a[mi][3],
                        AsJ + (uint32_t)(mi*16*BKP2*4 + kk*32));
            #pragma unroll
            for (int nip=0;nip<NI/2;nip++)
                ldsm_x4(b[2*nip][0], b[2*nip][1], b[2*nip+1][0], b[2*nip+1][1],
                        BsJ + (uint32_t)(nip*16*BKP2*4 + kk*32));
            #pragma unroll
            for (int mi=0;mi<MI;mi++)
                #pragma unroll
                for (int ni=0;ni<NI;ni++)
                    mma_bf16(acc[mi][ni], a[mi][0], a[mi][1], a[mi][2], a[mi][3],
                             b[ni][0], b[ni][1]);
        }
    }

    #pragma unroll
    for (int mi=0;mi<MI;mi++) {
        int r0 = m0 + wm0 + mi*16 + gid;
        int r1 = r0 + 8;
        float rs0 = cscale, rs1 = cscale;
        if (rowScale) {
            rs0 *= rowScale[z*rsStride + r0];
            rs1 *= rowScale[z*rsStride + r1];
        }
        #pragma unroll
        for (int ni=0;ni<NI;ni++) {
            int ccol = n0 + wn0 + ni*8 + tig*2;
            if (OUT_BF16) {
                uint32_t* Cb = (uint32_t*)Cv + ((long)(z/zdivC)*sC1 + (long)(z%zdivC)*sC2)/2;
                Cb[((long)r0*ldc + ccol) >> 1] = f2bf2(acc[mi][ni][0]*rs0, acc[mi][ni][1]*rs0);
                Cb[((long)r1*ldc + ccol) >> 1] = f2bf2(acc[mi][ni][2]*rs1, acc[mi][ni][3]*rs1);
            } else {
                float* C = (float*)Cv + (long)(z/zdivC)*sC1 + (long)(z%zdivC)*sC2;
                *(float2*)(C + (long)r0*ldc + ccol) =
                    make_float2(acc[mi][ni][0]*rs0, acc[mi][ni][1]*rs0);
                *(float2*)(C + (long)r1*ldc + ccol) =
                    make_float2(acc[mi][ni][2]*rs1, acc[mi][ni][3]*rs1);
            }
        }
    }
}

// ---------------- 4) attention: deferred-PV software pipeline ---------------
#define KR2 36
#define NCH 8
__global__ void __launch_bounds__(256, 2) attn_kernel(int bghOff)
{
    extern __shared__ uint32_t smem[];
    uint32_t* Ks = smem;
    uint32_t* Vs = smem + 4*64*KR2;
    float*    Ss = (float*)(smem + 8*64*KR2);

    const int bgh = blockIdx.y + bghOff;
    const int bg = bgh >> 3, h = bgh & 7;
    const int g  = bg & 3;
    const int m0q = blockIdx.x * 128;
    const int tid = threadIdx.x, warp = tid >> 5, lane = tid & 31;
    const int gid = lane >> 2, tig = lane & 3;
    const int wm = warp * 16;

    const __nv_bfloat16* Qbase = g_q + (size_t)bg*NQ_*DI_ + h*DH_;
    const __nv_bfloat16* KVb   = g_kv + (size_t)bg*NK_*2*DI_ + h*DH_;
    const __nv_bfloat16* nulK  = g_nullbf + ((0*G_+g)*H_ + h)*DH_;
    const __nv_bfloat16* nulV  = g_nullbf + ((1*G_+g)*H_ + h)*DH_;
    const float*         Sg    = g_sscale + bg*NKVP_;

    const int r0 = m0q + wm + gid, r1 = r0 + 8;

    auto prefetch = [&](int ch, int s) {
        const int j0 = ch * 64;
        uint32_t* Kd = Ks + s*64*KR2;
        uint32_t* Vd = Vs + s*64*KR2;
        #pragma unroll
        for (int f = tid; f < 64*8; f += 256) {
            int r = f >> 3, c = (f & 7) * 8;
            const __nv_bfloat16* base = KVb + (size_t)(j0 + r)*(2*DI_) + c;
            cp_async16(&Kd[r*KR2 + c/2], base);
            cp_async16(&Vd[r*KR2 + c/2], base + DI_);
        }
        if (tid < 16) cp_async16(&Ss[s*64 + tid*4], Sg + j0 + tid*4);
        cp_commit();
    };

    uint32_t aQ[4][4];
    #pragma unroll
    for (int kk = 0; kk < 4; kk++) {
        aQ[kk][0] = *(const uint32_t*)(Qbase + (size_t)r0*DI_ + kk*16 + 2*tig    );
        aQ[kk][1] = *(const uint32_t*)(Qbase + (size_t)r1*DI_ + kk*16 + 2*tig    );
        aQ[kk][2] = *(const uint32_t*)(Qbase + (size_t)r0*DI_ + kk*16 + 2*tig + 8);
        aQ[kk][3] = *(const uint32_t*)(Qbase + (size_t)r1*DI_ + kk*16 + 2*tig + 8);
    }

    const int lm = lane >> 3, lr = lane & 7;
    const uint32_t kLane = (uint32_t)((((lm>>1)*8 + lr)*KR2 + (lm&1)*4) * 4);
    const uint32_t vLane = (uint32_t)(((lm & 1)*8 + lr) * (KR2*4) + (lm >> 1)*16);
    const uint32_t KsA = (uint32_t)__cvta_generic_to_shared(Ks);
    const uint32_t VsA = (uint32_t)__cvta_generic_to_shared(Vs);

    // analytic null row
    float sn0 = 0.f, sn1 = 0.f;
    #pragma unroll
    for (int kk = 0; kk < 4; kk++) {
        float2 kn0 = bf2f2(*(const uint32_t*)(nulK + kk*16 + 2*tig    ));
        float2 kn1 = bf2f2(*(const uint32_t*)(nulK + kk*16 + 2*tig + 8));
        float2 a0 = bf2f2(aQ[kk][0]), a1 = bf2f2(aQ[kk][1]);
        float2 a2 = bf2f2(aQ[kk][2]), a3 = bf2f2(aQ[kk][3]);
        sn0 += a0.x*kn0.x + a0.y*kn0.y + a2.x*kn1.x + a2.y*kn1.y;
        sn1 += a1.x*kn0.x + a1.y*kn0.y + a3.x*kn1.x + a3.y*kn1.y;
    }
    sn0 += __shfl_xor_sync(0xffffffffu, sn0, 1);
    sn0 += __shfl_xor_sync(0xffffffffu, sn0, 2);
    sn1 += __shfl_xor_sync(0xffffffffu, sn1, 1);
    sn1 += __shfl_xor_sync(0xffffffffu, sn1, 2);
    const float pn0 = ex2f(sn0), pn1 = ex2f(sn1);

    float o[8][4];
    #pragma unroll
    for (int ni2 = 0; ni2 < 8; ni2++) {
        float2 vn = bf2f2(*(const uint32_t*)(nulV + ni2*8 + 2*tig));
        o[ni2][0] = pn0*vn.x; o[ni2][1] = pn0*vn.y;
        o[ni2][2] = pn1*vn.x; o[ni2][3] = pn1*vn.y;
    }
    float l0 = (tig == 0) ? pn0 : 0.f;
    float l1 = (tig == 0) ? pn1 : 0.f;

    uint32_t aP[4][4];
    int pvStage = 0;

    auto computeS = [&](int s, float sfr[8][4]) {
        const uint32_t KcA = KsA + (uint32_t)(s*64*KR2*4) + kLane;
        #pragma unroll
        for (int i=0;i<8;i++){ sfr[i][0]=0.f; sfr[i][1]=0.f; sfr[i][2]=0.f; sfr[i][3]=0.f; }
        #pragma unroll
        for (int kk = 0; kk < 4; kk++) {
            #pragma unroll
            for (int nip = 0; nip < 4; nip++) {
                uint32_t b0, b1, b2, b3;
                ldsm_x4(b0, b1, b2, b3, KcA + (uint32_t)(nip*16*KR2*4 + kk*32));
                mma_bf16(sfr[2*nip  ], aQ[kk][0], aQ[kk][1], aQ[kk][2], aQ[kk][3], b0, b1);
                mma_bf16(sfr[2*nip+1], aQ[kk][0], aQ[kk][1], aQ[kk][2], aQ[kk][3], b2, b3);
            }
        }
    };
    auto computePV = [&](int s) {
        const uint32_t VcA = VsA + (uint32_t)(s*64*KR2*4) + vLane;
        #pragma unroll
        for (int kk = 0; kk < 4; kk++) {
            #pragma unroll
            for (int np = 0; np < 4; np++) {
                uint32_t v0, v1, v2, v3;
                ldsm_x4_t(v0, v1, v2, v3, VcA + (uint32_t)(kk*16*(KR2*4) + np*32));
                mma_bf16(o[2*np  ], aP[kk][0], aP[kk][1], aP[kk][2], aP[kk][3], v0, v1);
                mma_bf16(o[2*np+1], aP[kk][0], aP[kk][1], aP[kk][2], aP[kk][3], v2, v3);
            }
        }
    };
    auto expPack = [&](int s, float sfr[8][4]) {
        const float* sc = Ss + s*64;
        #pragma unroll
        for (int ni = 0; ni < 8; ni++) {
            sfr[ni][0] = ex2f(sfr[ni][0]);
            sfr[ni][1] = ex2f(sfr[ni][1]);
            sfr[ni][2] = ex2f(sfr[ni][2]);
            sfr[ni][3] = ex2f(sfr[ni][3]);
            l0 += sfr[ni][0] + sfr[ni][1];
            l1 += sfr[ni][2] + sfr[ni][3];
        }
        #pragma unroll
        for (int kk = 0; kk < 4; kk++) {
            float2 sA = *(const float2*)&sc[kk*16 + 2*tig    ];
            float2 sB = *(const float2*)&sc[kk*16 + 2*tig + 8];
            aP[kk][0] = f2bf2(sfr[2*kk  ][0]*sA.x, sfr[2*kk  ][1]*sA.y);
            aP[kk][1] = f2bf2(sfr[2*kk  ][2]*sA.x, sfr[2*kk  ][3]*sA.y);
            aP[kk][2] = f2bf2(sfr[2*kk+1][0]*sB.x, sfr[2*kk+1][1]*sB.y);
            aP[kk][3] = f2bf2(sfr[2*kk+1][2]*sB.x, sfr[2*kk+1][3]*sB.y);
        }
    };

    prefetch(0, 0);
    prefetch(1, 1);
    cp_wait1();
    __syncthreads();
    prefetch(2, 2);
    {
        float sfr[8][4];
        computeS(0, sfr);
        expPack(0, sfr);
    }
    pvStage = 0;
    for (int ch = 1; ch < NCH; ch++) {
        if (ch + 1 < NCH) cp_wait1(); else cp_wait0();
        __syncthreads();
        if (ch + 2 < NCH) prefetch(ch + 2, (ch + 2) % 4);
        float sfr[8][4];
        computeS(ch % 4, sfr);
        computePV(pvStage);
        expPack(ch % 4, sfr);
        pvStage = ch % 4;
    }
    computePV(pvStage);

    l0 += __shfl_xor_sync(0xffffffffu, l0, 1);
    l0 += __shfl_xor_sync(0xffffffffu, l0, 2);
    l1 += __shfl_xor_sync(0xffffffffu, l1, 1);
    l1 += __shfl_xor_sync(0xffffffffu, l1, 2);
    float i0 = 1.f/l0, i1 = 1.f/l1;
    __nv_bfloat16* Obase = g_attno + (size_t)bg*NQ_*DI_ + h*DH_;
    #pragma unroll
    for (int ni2 = 0; ni2 < 8; ni2++) {
        int col = ni2*8 + 2*tig;
        *(uint32_t*)(Obase + (size_t)r0*DI_ + col) = f2bf2(o[ni2][0]*i0, o[ni2][1]*i0);
        *(uint32_t*)(Obase + (size_t)r1*DI_ + col) = f2bf2(o[ni2][2]*i1, o[ni2][3]*i1);
    }
}

// ---------------- 5) deterministic scatter-mean combine ---------------------
__global__ void combine_kernel(const float* __restrict__ null_token, float* __restrict__ out)
{
    int bn = blockIdx.x;
    int b = bn / N_, n = bn % N_;
    int tid = threadIdx.x;
    float4 acc = make_float4(0,0,0,0);
    int cnt = 0;
    #pragma unroll
    for (int g = 0; g < G_; g++) {
        int s = g_slot[(size_t)(b*G_+g)*N_ + n];
        if (s >= 0) {
            cnt++;
            float4 v = ((const float4*)(g_of + ((size_t)(b*G_+g)*NQ_ + s)*D_))[tid];
            acc.x+=v.x; acc.y+=v.y; acc.z+=v.z; acc.w+=v.w;
        }
    }
    float4 o;
    if (cnt > 0) {
        float inv = 1.f/(float)cnt;
        o = make_float4(acc.x*inv, acc.y*inv, acc.z*inv, acc.w*inv);
    } else {
        o = ((const float4*)null_token)[tid];
    }
    ((float4*)out)[(size_t)bn*(D_/4) + tid] = o;
}

// ---------------- launch ----------------------------------------------------
extern "C" void kernel_launch(void* const* d_in, const int* in_sizes, int n_in,
                              void* d_out, int out_size)
{
    const float* x          = (const float*)d_in[0];
    const float* w_qr       = (const float*)d_in[1];
    const float* w_kvr      = (const float*)d_in[2];
    const float* w_q        = (const float*)d_in[3];
    const float* w_kv       = (const float*)d_in[4];
    const float* w_out      = (const float*)d_in[5];
    const float* null_kv    = (const float*)d_in[6];
    const float* null_token = (const float*)d_in[7];
    float* out = (float*)d_out;

    __nv_bfloat16 *p_xbf,*p_wqbf,*p_wkvbf,*p_woutbf,*p_q,*p_kv,*p_attno;
    float *p_qscore,*p_of;
    int *p_qidx,*p_kvidx;
    cudaGetSymbolAddress((void**)&p_xbf,    g_xbf);
    cudaGetSymbolAddress((void**)&p_wqbf,   g_wqbf);
    cudaGetSymbolAddress((void**)&p_wkvbf,  g_wkvbf);
    cudaGetSymbolAddress((void**)&p_woutbf, g_woutbf);
    cudaGetSymbolAddress((void**)&p_q,      g_q);
    cudaGetSymbolAddress((void**)&p_kv,     g_kv);
    cudaGetSymbolAddress((void**)&p_attno,  g_attno);
    cudaGetSymbolAddress((void**)&p_qscore, g_qscore);
    cudaGetSymbolAddress((void**)&p_of,     g_of);
    cudaGetSymbolAddress((void**)&p_qidx,   g_qidx);
    cudaGetSymbolAddress((void**)&p_kvidx,  g_kvidx);

    constexpr int BKP2 = 20;
    constexpr size_t GEMM_SMEM = (size_t)(3*128*BKP2 + 3*128*BKP2)*4 + 128*4;   // 61952
    constexpr size_t ATTN_SMEM = (size_t)(8*64*KR2)*4 + 4*64*4;                 // 74752

    static cudaStream_t s1 = nullptr;
    static cudaEvent_t evFork = nullptr, evCvt = nullptr, evTopk = nullptr;
    static cudaEvent_t evKv = nullptr, evA0 = nullptr, evO0 = nullptr;
    static bool attr_done = false;
    if (!attr_done) {
        cudaFuncSetAttribute(mma_gemm<128,128,32,true,true>,
                             cudaFuncAttributeMaxDynamicSharedMemorySize, (int)GEMM_SMEM);
        cudaFuncSetAttribute(mma_gemm<128,128,32,false,false>,
                             cudaFuncAttributeMaxDynamicSharedMemorySize, (int)GEMM_SMEM);
        cudaFuncSetAttribute(attn_kernel,
                             cudaFuncAttributeMaxDynamicSharedMemorySize, (int)ATTN_SMEM);
        cudaStreamCreateWithFlags(&s1, cudaStreamNonBlocking);
        cudaEventCreateWithFlags(&evFork, cudaEventDisableTiming);
        cudaEventCreateWithFlags(&evCvt,  cudaEventDisableTiming);
        cudaEventCreateWithFlags(&evTopk, cudaEventDisableTiming);
        cudaEventCreateWithFlags(&evKv,   cudaEventDisableTiming);
        cudaEventCreateWithFlags(&evA0,   cudaEventDisableTiming);
        cudaEventCreateWithFlags(&evO0,   cudaEventDisableTiming);
        attr_done = true;
    }

    const int HZ = B_*G_/2;   // 8 z-blocks per half

    // fork: s1 converts weights while main does logits+topk
    cudaEventRecord(evFork, 0);
    cudaStreamWaitEvent(s1, evFork, 0);
    {
        int total4 = WQ4 + WKV4 + WOUT4 + NUL4;
        cvt_all<<<(total4 + 255)/256, 256, 0, s1>>>(w_q, w_kv, w_out, null_kv);
    }
    cudaEventRecord(evCvt, s1);

    logits_kernel<<<B_*N_/16, 512>>>(x, w_qr, w_kvr);
    topk_kernel<<<2*B_*G_, 1024>>>();
    cudaEventRecord(evTopk, 0);

    // s1: kv projection (full)
    cudaStreamWaitEvent(s1, evTopk, 0);
    {
        dim3 gr((2*DI_)/128, NK_/128, B_*G_);
        mma_gemm<128,128,32,true,true><<<gr,256,GEMM_SMEM,s1>>>(
            p_xbf, D_, G_, (long)N_*D_, 0L,
            p_wkvbf, D_, G_, 0L, (long)(2*DI_)*D_,
            p_kv, 2*DI_, 1, (long)NK_*2*DI_, 0L,
            D_, p_kvidx, NK_, nullptr, 0, 1.0f);
    }
    cudaEventRecord(evKv, s1);

    // main: q projection (full; DH^-0.5 * log2e fused)
    cudaStreamWaitEvent(0, evCvt, 0);
    {
        dim3 gr(DI_/128, NQ_/128, B_*G_);
        mma_gemm<128,128,32,true,true><<<gr,256,GEMM_SMEM>>>(
            p_xbf, D_, G_, (long)N_*D_, 0L,
            p_wqbf, D_, G_, 0L, (long)DI_*D_,
            p_q, DI_, 1, (long)NQ_*DI_, 0L,
            D_, p_qidx, NQ_, nullptr, 0, QSCALE);
    }

    // main: attention half 0 (bgh 0..63) after kvproj
    cudaStreamWaitEvent(0, evKv, 0);
    {
        dim3 gr(NQ_/128, HZ*H_);
        attn_kernel<<<gr, 256, ATTN_SMEM>>>(0);
    }
    cudaEventRecord(evA0, 0);

    // s1: out projection half 0 (z 0..7) overlapping attention half 1
    cudaStreamWaitEvent(s1, evA0, 0);
    {
        dim3 gr(D_/128, NQ_/128, HZ);
        mma_gemm<128,128,32,false,false><<<gr,256,GEMM_SMEM,s1>>>(
            p_attno, DI_, 1, (long)NQ_*DI_, 0L,
            p_woutbf, DI_, G_, 0L, (long)D_*DI_,
            p_of, D_, 1, (long)NQ_*D_, 0L,
            DI_, nullptr, 0, p_qscore, NQ_, 1.0f);
    }
    cudaEventRecord(evO0, s1);

    // main: attention half 1 (bgh 64..127)
    {
        dim3 gr(NQ_/128, HZ*H_);
        attn_kernel<<<gr, 256, ATTN_SMEM>>>(HZ*H_);
    }
    // main: out projection half 1 (z 8..15)
    {
        dim3 gr(D_/128, NQ_/128, HZ);
        mma_gemm<128,128,32,false,false><<<gr,256,GEMM_SMEM>>>(
            p_attno + (size_t)HZ*NQ_*DI_, DI_, 1, (long)NQ_*DI_, 0L,
            p_woutbf, DI_, G_, 0L, (long)D_*DI_,
            p_of + (size_t)HZ*NQ_*D_, D_, 1, (long)NQ_*D_, 0L,
            DI_, nullptr, 0, p_qscore + HZ*NQ_, NQ_, 1.0f);
    }
    // main: combine after both out-proj halves
    cudaStreamWaitEvent(0, evO0, 0);
    combine_kernel<<<B_*N_, 256>>>(null_token, out);
}

// round 17
// speedup vs baseline: 1.0426x; 1.0426x over previous
#include <cuda_runtime.h>
#include <cuda_bf16.h>
#include <cuda_fp16.h>
#include <cstdint>
#include <math.h>

#define B_ 4
#define N_ 4096
#define D_ 1024
#define G_ 4
#define H_ 8
#define DH_ 64
#define DI_ 512
#define NQ_ 1024
#define NK_ 512
#define NKV_ 513
#define NKVP_ 576

// ---------------- scratch ---------------------------------------------------
__device__ float         g_qlog [B_*G_*N_];
__device__ float         g_kvlog[B_*G_*N_];
__device__ int           g_qidx [B_*G_*NQ_];
__device__ float         g_qscore[B_*G_*NQ_];
__device__ int           g_kvidx [B_*G_*NK_];
__device__ float         g_sscale[B_*G_*NKVP_];
__device__ int           g_slot [B_*G_*N_];
__device__ __nv_bfloat16 g_xbf  [B_*N_*D_];
__device__ __nv_bfloat16 g_wqbf [G_*DI_*D_];
__device__ __nv_bfloat16 g_wkvbf[G_*2*DI_*D_];
__device__ __nv_bfloat16 g_woutbf[G_*D_*DI_];
__device__ __nv_bfloat16 g_nullbf[2*G_*H_*DH_];
__device__ __nv_bfloat16 g_q    [B_*G_*NQ_*DI_];
__device__ __nv_bfloat16 g_kv   [B_*G_*NK_*2*DI_];
__device__ __nv_bfloat16 g_attno[B_*G_*NQ_*DI_];
__device__ __half        g_of   [(size_t)B_*G_*NQ_*D_];   // fp16: halves of/combine traffic

#define QSCALE 0.18033688f   // DH^-0.5 * log2(e)

// ---------------- helpers ---------------------------------------------------
__device__ __forceinline__ uint32_t f2bf2(float lo, float hi) {
    uint32_t r;
    asm("cvt.rn.bf16x2.f32 %0, %1, %2;" : "=r"(r) : "f"(hi), "f"(lo));
    return r;
}
__device__ __forceinline__ float2 bf2f2(uint32_t v) {
    __nv_bfloat162 b = *(__nv_bfloat162*)&v;
    return __bfloat1622float2(b);
}
__device__ __forceinline__ float ex2f(float x) {
    float y;
    asm("ex2.approx.f32 %0, %1;" : "=f"(y) : "f"(x));
    return y;
}
__device__ __forceinline__ void mma_bf16(float c[4],
                                         uint32_t a0, uint32_t a1, uint32_t a2, uint32_t a3,
                                         uint32_t b0, uint32_t b1) {
    asm volatile(
        "mma.sync.aligned.m16n8k16.row.col.f32.bf16.bf16.f32 "
        "{%0,%1,%2,%3}, {%4,%5,%6,%7}, {%8,%9}, {%0,%1,%2,%3};\n"
        : "+f"(c[0]), "+f"(c[1]), "+f"(c[2]), "+f"(c[3])
        : "r"(a0), "r"(a1), "r"(a2), "r"(a3), "r"(b0), "r"(b1));
}
__device__ __forceinline__ void ldsm_x4(uint32_t& r0, uint32_t& r1, uint32_t& r2, uint32_t& r3,
                                        uint32_t addr) {
    asm volatile("ldmatrix.sync.aligned.m8n8.x4.shared.b16 {%0,%1,%2,%3}, [%4];"
                 : "=r"(r0), "=r"(r1), "=r"(r2), "=r"(r3) : "r"(addr));
}
__device__ __forceinline__ void ldsm_x4_t(uint32_t& r0, uint32_t& r1, uint32_t& r2, uint32_t& r3,
                                          uint32_t addr) {
    asm volatile("ldmatrix.sync.aligned.m8n8.x4.trans.shared.b16 {%0,%1,%2,%3}, [%4];"
                 : "=r"(r0), "=r"(r1), "=r"(r2), "=r"(r3) : "r"(addr));
}
__device__ __forceinline__ void cp_async16(void* smem_dst, const void* gmem_src) {
    uint32_t s = (uint32_t)__cvta_generic_to_shared(smem_dst);
    asm volatile("cp.async.cg.shared.global [%0], [%1], 16;\n" :: "r"(s), "l"(gmem_src));
}
__device__ __forceinline__ void cp_commit() { asm volatile("cp.async.commit_group;\n"); }
__device__ __forceinline__ void cp_wait0() { asm volatile("cp.async.wait_group 0;\n"); }
__device__ __forceinline__ void cp_wait1() { asm volatile("cp.async.wait_group 1;\n"); }

// ---------------- 0) fp32 -> bf16 convert (weights + null_kv) ---------------
#define WQ4   (G_*DI_*D_/4)
#define WKV4  (G_*2*DI_*D_/4)
#define WOUT4 (G_*D_*DI_/4)
#define NUL4  (2*G_*H_*DH_/4)
__device__ __forceinline__ void cvt4(const float* s, __nv_bfloat16* d, int i) {
    float4 v = ((const float4*)s)[i];
    ((uint2*)d)[i] = make_uint2(f2bf2(v.x, v.y), f2bf2(v.z, v.w));
}
__global__ void cvt_all(const float* __restrict__ wq, const float* __restrict__ wkv,
                        const float* __restrict__ wout, const float* __restrict__ nul)
{
    int i = blockIdx.x*256 + threadIdx.x;
    if (i < WQ4) { cvt4(wq, g_wqbf, i); return; }
    i -= WQ4;
    if (i < WKV4) { cvt4(wkv, g_wkvbf, i); return; }
    i -= WKV4;
    if (i < WOUT4) { cvt4(wout, g_woutbf, i); return; }
    i -= WOUT4;
    if (i < NUL4) cvt4(nul, g_nullbf, i);
}

// ---------------- 1) router logits (fp32) + x -> bf16 -----------------------
__global__ void __launch_bounds__(512) logits_kernel(const float* __restrict__ x,
                                                     const float* __restrict__ w_qr,
                                                     const float* __restrict__ w_kvr)
{
    __shared__ float ws[8*D_];
    int tid = threadIdx.x;
    for (int i = tid; i < 4*D_; i += 512) { ws[i] = w_qr[i]; ws[4*D_+i] = w_kvr[i]; }
    __syncthreads();
    int warp = tid >> 5, lane = tid & 31;
    int tok = blockIdx.x*16 + warp;
    int b = tok / N_, n = tok % N_;
    const float4* xr = (const float4*)(x + (size_t)tok*D_);
    uint2* xt = (uint2*)(g_xbf + (size_t)tok*D_);
    float acc[8] = {0,0,0,0,0,0,0,0};
    #pragma unroll
    for (int it = 0; it < 8; it++) {
        int k4 = lane + it*32;
        float4 xv = xr[k4];
        xt[k4] = make_uint2(f2bf2(xv.x, xv.y), f2bf2(xv.z, xv.w));
        #pragma unroll
        for (int g = 0; g < 8; g++) {
            float4 w4 = *(const float4*)(ws + g*D_ + k4*4);
            acc[g] += xv.x*w4.x + xv.y*w4.y + xv.z*w4.z + xv.w*w4.w;
        }
    }
    #pragma unroll
    for (int g = 0; g < 8; g++) {
        #pragma unroll
        for (int o = 16; o > 0; o >>= 1) acc[g] += __shfl_xor_sync(0xffffffffu, acc[g], o);
    }
    if (lane < 4) {
        g_qlog[(b*G_+lane)*N_ + n] = acc[lane];
        g_slot[(b*G_+lane)*N_ + n] = -1;
    } else if (lane < 8) {
        g_kvlog[(b*G_+(lane-4))*N_ + n] = acc[lane];
    }
}

// ---------------- 2) exact top-k via deterministic radix select -------------
__global__ void __launch_bounds__(1024) topk_kernel()
{
    __shared__ uint32_t su[N_];
    __shared__ int hist[256];
    __shared__ int wsum[32];
    __shared__ int sBase;
    __shared__ uint32_t sPref;
    __shared__ int sK;

    const bool isq = blockIdx.x < (B_*G_);
    const int bg = isq ? blockIdx.x : blockIdx.x - B_*G_;
    const int ksel = isq ? NQ_ : NK_;
    const float* L = (isq ? g_qlog : g_kvlog) + (size_t)bg*N_;
    const int tid = threadIdx.x, warp = tid >> 5, lane = tid & 31;

    for (int i = tid; i < N_; i += 1024) {
        uint32_t u = __float_as_uint(L[i]);
        su[i] = (u & 0x80000000u) ? ~u : (u | 0x80000000u);
    }
    if (tid == 0) { sK = ksel; sPref = 0; sBase = 0; }
    __syncthreads();

    for (int p = 0; p < 4; p++) {
        const int shift = 24 - 8*p;
        for (int i = tid; i < 256; i += 1024) hist[i] = 0;
        __syncthreads();
        const uint32_t pref = sPref;
        const int kk = sK;
        for (int i = tid; i < N_; i += 1024) {
            uint32_t u = su[i];
            bool act = (p == 0) ? true : ((u >> (shift + 8)) == pref);
            if (act) atomicAdd(&hist[(u >> shift) & 0xFF], 1);
        }
        __syncthreads();
        if (tid == 0) {
            int acc = 0, b = 255;
            for (; b > 0; b--) {
                if (acc + hist[b] >= kk) break;
                acc += hist[b];
            }
            sPref = (p == 0) ? (uint32_t)b : ((pref << 8) | (uint32_t)b);
            sK = kk - acc;
        }
        __syncthreads();
    }
    const uint32_t T = sPref;
    for (int pass = 0; pass < 2; pass++) {
        for (int r = 0; r < 4; r++) {
            const int i = r*1024 + tid;
            const uint32_t u = su[i];
            const bool sel = pass == 0 ? (u > T) : (u == T);
            const uint32_t bal = __ballot_sync(0xffffffffu, sel);
            const int wpre = __popc(bal & ((1u << lane) - 1u));
            if (lane == 0) wsum[warp] = __popc(bal);
            __syncthreads();
            if (tid == 0) {
                int run = sBase;
                #pragma unroll
                for (int w = 0; w < 32; w++) { int c = wsum[w]; wsum[w] = run; run += c; }
                sBase = run;
            }
            __syncthreads();
            if (sel) {
                int pos = wsum[warp] + wpre;
                if (pos < ksel) {
                    uint32_t ob = (u & 0x80000000u) ? (u ^ 0x80000000u) : ~u;
                    float f = __uint_as_float(ob);
                    float score = 1.0f/(1.0f + expf(-f));
                    if (isq) {
                        g_qidx[bg*NQ_ + pos]   = i;
                        g_qscore[bg*NQ_ + pos] = score;
                        g_slot[(size_t)bg*N_ + i] = pos;
                    } else {
                        g_kvidx[bg*NK_ + pos] = i;
                        g_sscale[bg*NKVP_ + pos] = score;
                    }
                }
            }
            __syncthreads();
        }
    }
}

// ---------------- 3) 3-stage bf16 GEMM, one sync per chunk ------------------
// OUTM: 1 = bf16 out, 2 = fp16 out
template<int BM,int BN,int BK,bool GATHER,int OUTM>
__global__ void __launch_bounds__(256, 2)
mma_gemm(const __nv_bfloat16* __restrict__ A, int lda, int zdivA, long sA1, long sA2,
         const __nv_bfloat16* __restrict__ Bp, int ldb, int zdivB, long sB1, long sB2,
         void* __restrict__ Cv, int ldc, int zdivC, long sC1, long sC2,
         int K,
         const int* __restrict__ gidx, int gstride,
         const float* __restrict__ rowScale, int rsStride,
         float cscale)
{
    constexpr int WM = BM/2, WN = BN/4;
    constexpr int MI = WM/16, NI = WN/8;
    constexpr int BKP2 = BK/2 + 4;
    constexpr int ASTG = BM*BKP2, BSTG = BN*BKP2;

    extern __shared__ uint32_t dsm[];
    uint32_t* Asf = dsm;
    uint32_t* Bsf = dsm + 3*ASTG;
    int*      ridx = (int*)(dsm + 3*ASTG + 3*BSTG);

    const int z = blockIdx.z;
    A  += (long)(z/zdivA)*sA1 + (long)(z%zdivA)*sA2;
    Bp += (long)(z/zdivB)*sB1 + (long)(z%zdivB)*sB2;
    const int m0 = blockIdx.y*BM, n0 = blockIdx.x*BN;
    const int tid  = threadIdx.x;
    const int warp = tid >> 5, lane = tid & 31;
    const int gid  = lane >> 2, tig = lane & 3;
    const int wm0  = (warp >> 2) * WM;
    const int wn0  = (warp & 3) * WN;

    if (GATHER) {
        for (int i = tid; i < BM; i += 256) ridx[i] = gidx[z*gstride + m0 + i];
        __syncthreads();
    }

    auto prefetch = [&](int k0, int s) {
        uint32_t* As_ = Asf + s*ASTG;
        #pragma unroll
        for (int f = tid; f < BM*(BK/8); f += 256) {
            int m = f / (BK/8), c = f % (BK/8);
            long row = GATHER ? (long)ridx[m] : (long)(m0+m);
            cp_async16(&As_[m*BKP2 + c*4], A + row*(long)lda + k0 + c*8);
        }
        uint32_t* Bs_ = Bsf + s*BSTG;
        #pragma unroll
        for (int f = tid; f < BN*(BK/8); f += 256) {
            int nn = f / (BK/8), c = f % (BK/8);
            cp_async16(&Bs_[nn*BKP2 + c*4], Bp + (long)(n0+nn)*ldb + k0 + c*8);
        }
        cp_commit();
    };

    float acc[MI][NI][4];
    #pragma unroll
    for (int mi=0;mi<MI;mi++)
        #pragma unroll
        for (int ni=0;ni<NI;ni++)
            #pragma unroll
            for (int r=0;r<4;r++) acc[mi][ni][r] = 0.f;

    const uint32_t AsA = (uint32_t)__cvta_generic_to_shared(Asf);
    const uint32_t BsA = (uint32_t)__cvta_generic_to_shared(Bsf);
    const int lm = lane >> 3, lr = lane & 7;
    const uint32_t aLane = (uint32_t)(((wm0 + (lm&1)*8 + lr)*BKP2 + (lm>>1)*4) * 4);
    const uint32_t bLane = (uint32_t)(((wn0 + (lm>>1)*8 + lr)*BKP2 + (lm&1)*4) * 4);

    const int NKIT = K / BK;
    prefetch(0, 0);
    if (NKIT > 1) prefetch(BK, 1);
    for (int j = 0; j < NKIT; j++) {
        if (j + 1 < NKIT) cp_wait1(); else cp_wait0();
        __syncthreads();
        if (j + 2 < NKIT) prefetch((j+2)*BK, (j+2)%3);

        const uint32_t AsJ = AsA + (uint32_t)((j%3)*ASTG*4) + aLane;
        const uint32_t BsJ = BsA + (uint32_t)((j%3)*BSTG*4) + bLane;
        #pragma unroll
        for (int kk = 0; kk < BK/16; kk++) {
            uint32_t a[MI][4];
            uint32_t b[NI][2];
            #pragma unroll
            for (int mi=0;mi<MI;mi++)
                ldsm_x4(a[mi][0], a[mi][1], a[mi][2], a[mi][3],
                        AsJ + (uint32_t)(mi*16*BKP2*4 + kk*32));
            #pragma unroll
            for (int nip=0;nip<NI/2;nip++)
                ldsm_x4(b[2*nip][0], b[2*nip][1], b[2*nip+1][0], b[2*nip+1][1],
                        BsJ + (uint32_t)(nip*16*BKP2*4 + kk*32));
            #pragma unroll
            for (int mi=0;mi<MI;mi++)
                #pragma unroll
                for (int ni=0;ni<NI;ni++)
                    mma_bf16(acc[mi][ni], a[mi][0], a[mi][1], a[mi][2], a[mi][3],
                             b[ni][0], b[ni][1]);
        }
    }

    #pragma unroll
    for (int mi=0;mi<MI;mi++) {
        int r0 = m0 + wm0 + mi*16 + gid;
        int r1 = r0 + 8;
        float rs0 = cscale, rs1 = cscale;
        if (rowScale) {
            rs0 *= rowScale[z*rsStride + r0];
            rs1 *= rowScale[z*rsStride + r1];
        }
        #pragma unroll
        for (int ni=0;ni<NI;ni++) {
            int ccol = n0 + wn0 + ni*8 + tig*2;
            uint32_t* Cb = (uint32_t*)Cv + ((long)(z/zdivC)*sC1 + (long)(z%zdivC)*sC2)/2;
            if (OUTM == 1) {
                Cb[((long)r0*ldc + ccol) >> 1] = f2bf2(acc[mi][ni][0]*rs0, acc[mi][ni][1]*rs0);
                Cb[((long)r1*ldc + ccol) >> 1] = f2bf2(acc[mi][ni][2]*rs1, acc[mi][ni][3]*rs1);
            } else {
                __half2 h0 = __floats2half2_rn(acc[mi][ni][0]*rs0, acc[mi][ni][1]*rs0);
                __half2 h1 = __floats2half2_rn(acc[mi][ni][2]*rs1, acc[mi][ni][3]*rs1);
                Cb[((long)r0*ldc + ccol) >> 1] = *(uint32_t*)&h0;
                Cb[((long)r1*ldc + ccol) >> 1] = *(uint32_t*)&h1;
            }
        }
    }
}

// ---------------- 4) attention: deferred-PV software pipeline ---------------
#define KR2 36
#define NCH 8
__global__ void __launch_bounds__(256, 2) attn_kernel()
{
    extern __shared__ uint32_t smem[];
    uint32_t* Ks = smem;
    uint32_t* Vs = smem + 4*64*KR2;
    float*    Ss = (float*)(smem + 8*64*KR2);

    const int bgh = blockIdx.y;
    const int bg = bgh >> 3, h = bgh & 7;
    const int g  = bg & 3;
    const int m0q = blockIdx.x * 128;
    const int tid = threadIdx.x, warp = tid >> 5, lane = tid & 31;
    const int gid = lane >> 2, tig = lane & 3;
    const int wm = warp * 16;

    const __nv_bfloat16* Qbase = g_q + (size_t)bg*NQ_*DI_ + h*DH_;
    const __nv_bfloat16* KVb   = g_kv + (size_t)bg*NK_*2*DI_ + h*DH_;
    const __nv_bfloat16* nulK  = g_nullbf + ((0*G_+g)*H_ + h)*DH_;
    const __nv_bfloat16* nulV  = g_nullbf + ((1*G_+g)*H_ + h)*DH_;
    const float*         Sg    = g_sscale + bg*NKVP_;

    const int r0 = m0q + wm + gid, r1 = r0 + 8;

    auto prefetch = [&](int ch, int s) {
        const int j0 = ch * 64;
        uint32_t* Kd = Ks + s*64*KR2;
        uint32_t* Vd = Vs + s*64*KR2;
        #pragma unroll
        for (int f = tid; f < 64*8; f += 256) {
            int r = f >> 3, c = (f & 7) * 8;
            const __nv_bfloat16* base = KVb + (size_t)(j0 + r)*(2*DI_) + c;
            cp_async16(&Kd[r*KR2 + c/2], base);
            cp_async16(&Vd[r*KR2 + c/2], base + DI_);
        }
        if (tid < 16) cp_async16(&Ss[s*64 + tid*4], Sg + j0 + tid*4);
        cp_commit();
    };

    uint32_t aQ[4][4];
    #pragma unroll
    for (int kk = 0; kk < 4; kk++) {
        aQ[kk][0] = *(const uint32_t*)(Qbase + (size_t)r0*DI_ + kk*16 + 2*tig    );
        aQ[kk][1] = *(const uint32_t*)(Qbase + (size_t)r1*DI_ + kk*16 + 2*tig    );
        aQ[kk][2] = *(const uint32_t*)(Qbase + (size_t)r0*DI_ + kk*16 + 2*tig + 8);
        aQ[kk][3] = *(const uint32_t*)(Qbase + (size_t)r1*DI_ + kk*16 + 2*tig + 8);
    }

    const int lm = lane >> 3, lr = lane & 7;
    const uint32_t kLane = (uint32_t)((((lm>>1)*8 + lr)*KR2 + (lm&1)*4) * 4);
    const uint32_t vLane = (uint32_t)(((lm & 1)*8 + lr) * (KR2*4) + (lm >> 1)*16);
    const uint32_t KsA = (uint32_t)__cvta_generic_to_shared(Ks);
    const uint32_t VsA = (uint32_t)__cvta_generic_to_shared(Vs);

    // analytic null row (Q pre-scaled by DH^-0.5 * log2e)
    float sn0 = 0.f, sn1 = 0.f;
    #pragma unroll
    for (int kk = 0; kk < 4; kk++) {
        float2 kn0 = bf2f2(*(const uint32_t*)(nulK + kk*16 + 2*tig    ));
        float2 kn1 = bf2f2(*(const uint32_t*)(nulK + kk*16 + 2*tig + 8));
        float2 a0 = bf2f2(aQ[kk][0]), a1 = bf2f2(aQ[kk][1]);
        float2 a2 = bf2f2(aQ[kk][2]), a3 = bf2f2(aQ[kk][3]);
        sn0 += a0.x*kn0.x + a0.y*kn0.y + a2.x*kn1.x + a2.y*kn1.y;
        sn1 += a1.x*kn0.x + a1.y*kn0.y + a3.x*kn1.x + a3.y*kn1.y;
    }
    sn0 += __shfl_xor_sync(0xffffffffu, sn0, 1);
    sn0 += __shfl_xor_sync(0xffffffffu, sn0, 2);
    sn1 += __shfl_xor_sync(0xffffffffu, sn1, 1);
    sn1 += __shfl_xor_sync(0xffffffffu, sn1, 2);
    const float pn0 = ex2f(sn0), pn1 = ex2f(sn1);

    float o[8][4];
    #pragma unroll
    for (int ni2 = 0; ni2 < 8; ni2++) {
        float2 vn = bf2f2(*(const uint32_t*)(nulV + ni2*8 + 2*tig));
        o[ni2][0] = pn0*vn.x; o[ni2][1] = pn0*vn.y;
        o[ni2][2] = pn1*vn.x; o[ni2][3] = pn1*vn.y;
    }
    float l0 = (tig == 0) ? pn0 : 0.f;
    float l1 = (tig == 0) ? pn1 : 0.f;

    uint32_t aP[4][4];
    int pvStage = 0;

    auto computeS = [&](int s, float sfr[8][4]) {
        const uint32_t KcA = KsA + (uint32_t)(s*64*KR2*4) + kLane;
        #pragma unroll
        for (int i=0;i<8;i++){ sfr[i][0]=0.f; sfr[i][1]=0.f; sfr[i][2]=0.f; sfr[i][3]=0.f; }
        #pragma unroll
        for (int kk = 0; kk < 4; kk++) {
            #pragma unroll
            for (int nip = 0; nip < 4; nip++) {
                uint32_t b0, b1, b2, b3;
                ldsm_x4(b0, b1, b2, b3, KcA + (uint32_t)(nip*16*KR2*4 + kk*32));
                mma_bf16(sfr[2*nip  ], aQ[kk][0], aQ[kk][1], aQ[kk][2], aQ[kk][3], b0, b1);
                mma_bf16(sfr[2*nip+1], aQ[kk][0], aQ[kk][1], aQ[kk][2], aQ[kk][3], b2, b3);
            }
        }
    };
    auto computePV = [&](int s) {
        const uint32_t VcA = VsA + (uint32_t)(s*64*KR2*4) + vLane;
        #pragma unroll
        for (int kk = 0; kk < 4; kk++) {
            #pragma unroll
            for (int np = 0; np < 4; np++) {
                uint32_t v0, v1, v2, v3;
                ldsm_x4_t(v0, v1, v2, v3, VcA + (uint32_t)(kk*16*(KR2*4) + np*32));
                mma_bf16(o[2*np  ], aP[kk][0], aP[kk][1], aP[kk][2], aP[kk][3], v0, v1);
                mma_bf16(o[2*np+1], aP[kk][0], aP[kk][1], aP[kk][2], aP[kk][3], v2, v3);
            }
        }
    };
    auto expPack = [&](int s, float sfr[8][4]) {
        const float* sc = Ss + s*64;
        #pragma unroll
        for (int ni = 0; ni < 8; ni++) {
            sfr[ni][0] = ex2f(sfr[ni][0]);
            sfr[ni][1] = ex2f(sfr[ni][1]);
            sfr[ni][2] = ex2f(sfr[ni][2]);
            sfr[ni][3] = ex2f(sfr[ni][3]);
            l0 += sfr[ni][0] + sfr[ni][1];
            l1 += sfr[ni][2] + sfr[ni][3];
        }
        #pragma unroll
        for (int kk = 0; kk < 4; kk++) {
            float2 sA = *(const float2*)&sc[kk*16 + 2*tig    ];
            float2 sB = *(const float2*)&sc[kk*16 + 2*tig + 8];
            aP[kk][0] = f2bf2(sfr[2*kk  ][0]*sA.x, sfr[2*kk  ][1]*sA.y);
            aP[kk][1] = f2bf2(sfr[2*kk  ][2]*sA.x, sfr[2*kk  ][3]*sA.y);
            aP[kk][2] = f2bf2(sfr[2*kk+1][0]*sB.x, sfr[2*kk+1][1]*sB.y);
            aP[kk][3] = f2bf2(sfr[2*kk+1][2]*sB.x, sfr[2*kk+1][3]*sB.y);
        }
    };

    prefetch(0, 0);
    prefetch(1, 1);
    cp_wait1();
    __syncthreads();
    prefetch(2, 2);
    {
        float sfr[8][4];
        computeS(0, sfr);
        expPack(0, sfr);
    }
    pvStage = 0;
    for (int ch = 1; ch < NCH; ch++) {
        if (ch + 1 < NCH) cp_wait1(); else cp_wait0();
        __syncthreads();
        if (ch + 2 < NCH) prefetch(ch + 2, (ch + 2) % 4);
        float sfr[8][4];
        computeS(ch % 4, sfr);
        computePV(pvStage);
        expPack(ch % 4, sfr);
        pvStage = ch % 4;
    }
    computePV(pvStage);

    l0 += __shfl_xor_sync(0xffffffffu, l0, 1);
    l0 += __shfl_xor_sync(0xffffffffu, l0, 2);
    l1 += __shfl_xor_sync(0xffffffffu, l1, 1);
    l1 += __shfl_xor_sync(0xffffffffu, l1, 2);
    float i0 = 1.f/l0, i1 = 1.f/l1;
    __nv_bfloat16* Obase = g_attno + (size_t)bg*NQ_*DI_ + h*DH_;
    #pragma unroll
    for (int ni2 = 0; ni2 < 8; ni2++) {
        int col = ni2*8 + 2*tig;
        *(uint32_t*)(Obase + (size_t)r0*DI_ + col) = f2bf2(o[ni2][0]*i0, o[ni2][1]*i0);
        *(uint32_t*)(Obase + (size_t)r1*DI_ + col) = f2bf2(o[ni2][2]*i1, o[ni2][3]*i1);
    }
}

// ---------------- 5) deterministic scatter-mean combine (fp16 g_of) ---------
__global__ void combine_kernel(const float* __restrict__ null_token, float* __restrict__ out)
{
    int bn = blockIdx.x;
    int b = bn / N_, n = bn % N_;
    int tid = threadIdx.x;
    float4 acc = make_float4(0,0,0,0);
    int cnt = 0;
    #pragma unroll
    for (int g = 0; g < G_; g++) {
        int s = g_slot[(size_t)(b*G_+g)*N_ + n];
        if (s >= 0) {
            cnt++;
            uint2 u = ((const uint2*)(g_of + ((size_t)(b*G_+g)*NQ_ + s)*D_))[tid];
            float2 f0 = __half22float2(*(__half2*)&u.x);
            float2 f1 = __half22float2(*(__half2*)&u.y);
            acc.x+=f0.x; acc.y+=f0.y; acc.z+=f1.x; acc.w+=f1.y;
        }
    }
    float4 o;
    if (cnt > 0) {
        float inv = 1.f/(float)cnt;
        o = make_float4(acc.x*inv, acc.y*inv, acc.z*inv, acc.w*inv);
    } else {
        o = ((const float4*)null_token)[tid];
    }
    ((float4*)out)[(size_t)bn*(D_/4) + tid] = o;
}

// ---------------- launch ----------------------------------------------------
extern "C" void kernel_launch(void* const* d_in, const int* in_sizes, int n_in,
                              void* d_out, int out_size)
{
    const float* x          = (const float*)d_in[0];
    const float* w_qr       = (const float*)d_in[1];
    const float* w_kvr      = (const float*)d_in[2];
    const float* w_q        = (const float*)d_in[3];
    const float* w_kv       = (const float*)d_in[4];
    const float* w_out      = (const float*)d_in[5];
    const float* null_kv    = (const float*)d_in[6];
    const float* null_token = (const float*)d_in[7];
    float* out = (float*)d_out;

    __nv_bfloat16 *p_xbf,*p_wqbf,*p_wkvbf,*p_woutbf,*p_q,*p_kv,*p_attno;
    __half *p_of;
    float *p_qscore;
    int *p_qidx,*p_kvidx;
    cudaGetSymbolAddress((void**)&p_xbf,    g_xbf);
    cudaGetSymbolAddress((void**)&p_wqbf,   g_wqbf);
    cudaGetSymbolAddress((void**)&p_wkvbf,  g_wkvbf);
    cudaGetSymbolAddress((void**)&p_woutbf, g_woutbf);
    cudaGetSymbolAddress((void**)&p_q,      g_q);
    cudaGetSymbolAddress((void**)&p_kv,     g_kv);
    cudaGetSymbolAddress((void**)&p_attno,  g_attno);
    cudaGetSymbolAddress((void**)&p_qscore, g_qscore);
    cudaGetSymbolAddress((void**)&p_of,     g_of);
    cudaGetSymbolAddress((void**)&p_qidx,   g_qidx);
    cudaGetSymbolAddress((void**)&p_kvidx,  g_kvidx);

    constexpr int BKP2 = 20;
    constexpr size_t GEMM_SMEM = (size_t)(3*128*BKP2 + 3*128*BKP2)*4 + 128*4;   // 61952
    constexpr size_t ATTN_SMEM = (size_t)(8*64*KR2)*4 + 4*64*4;                 // 74752

    static cudaStream_t s1 = nullptr;
    static cudaEvent_t evFork = nullptr, evCvt = nullptr, evTopk = nullptr, evKv = nullptr;
    static bool attr_done = false;
    if (!attr_done) {
        cudaFuncSetAttribute(mma_gemm<128,128,32,true,1>,
                             cudaFuncAttributeMaxDynamicSharedMemorySize, (int)GEMM_SMEM);
        cudaFuncSetAttribute(mma_gemm<128,128,32,false,2>,
                             cudaFuncAttributeMaxDynamicSharedMemorySize, (int)GEMM_SMEM);
        cudaFuncSetAttribute(attn_kernel,
                             cudaFuncAttributeMaxDynamicSharedMemorySize, (int)ATTN_SMEM);
        cudaStreamCreateWithFlags(&s1, cudaStreamNonBlocking);
        cudaEventCreateWithFlags(&evFork, cudaEventDisableTiming);
        cudaEventCreateWithFlags(&evCvt,  cudaEventDisableTiming);
        cudaEventCreateWithFlags(&evTopk, cudaEventDisableTiming);
        cudaEventCreateWithFlags(&evKv,   cudaEventDisableTiming);
        attr_done = true;
    }

    // fork: s1 converts weights while main does logits+topk
    cudaEventRecord(evFork, 0);
    cudaStreamWaitEvent(s1, evFork, 0);
    {
        int total4 = WQ4 + WKV4 + WOUT4 + NUL4;
        cvt_all<<<(total4 + 255)/256, 256, 0, s1>>>(w_q, w_kv, w_out, null_kv);
    }
    cudaEventRecord(evCvt, s1);

    logits_kernel<<<B_*N_/16, 512>>>(x, w_qr, w_kvr);
    topk_kernel<<<2*B_*G_, 1024>>>();
    cudaEventRecord(evTopk, 0);

    // s1: kv projection
    cudaStreamWaitEvent(s1, evTopk, 0);
    {
        dim3 gr((2*DI_)/128, NK_/128, B_*G_);
        mma_gemm<128,128,32,true,1><<<gr,256,GEMM_SMEM,s1>>>(
            p_xbf, D_, G_, (long)N_*D_, 0L,
            p_wkvbf, D_, G_, 0L, (long)(2*DI_)*D_,
            p_kv, 2*DI_, 1, (long)NK_*2*DI_, 0L,
            D_, p_kvidx, NK_, nullptr, 0, 1.0f);
    }
    cudaEventRecord(evKv, s1);

    // main: q projection (DH^-0.5 * log2e fused)
    cudaStreamWaitEvent(0, evCvt, 0);
    {
        dim3 gr(DI_/128, NQ_/128, B_*G_);
        mma_gemm<128,128,32,true,1><<<gr,256,GEMM_SMEM>>>(
            p_xbf, D_, G_, (long)N_*D_, 0L,
            p_wqbf, D_, G_, 0L, (long)DI_*D_,
            p_q, DI_, 1, (long)NQ_*DI_, 0L,
            D_, p_qidx, NQ_, nullptr, 0, QSCALE);
    }

    // join -> attention (full grid)
    cudaStreamWaitEvent(0, evKv, 0);
    {
        dim3 gr(NQ_/128, B_*G_*H_);
        attn_kernel<<<gr, 256, ATTN_SMEM>>>();
    }
    // out projection + q_score row scaling (fp16 out)
    {
        dim3 gr(D_/128, NQ_/128, B_*G_);
        mma_gemm<128,128,32,false,2><<<gr,256,GEMM_SMEM>>>(
            p_attno, DI_, 1, (long)NQ_*DI_, 0L,
            p_woutbf, DI_, G_, 0L, (long)D_*DI_,
            p_of, D_, 1, (long)NQ_*D_, 0L,
            DI_, nullptr, 0, p_qscore, NQ_, 1.0f);
    }
    combine_kernel<<<B_*N_, 256>>>(null_token, out);
}